// round 12
// baseline (speedup 1.0000x reference)
#include <cuda_runtime.h>
#include <cuda_bf16.h>
#include <cstdint>
#include <math.h>

#define BATCH 32768
#define DIM   1024
#define HID   256

typedef __nv_bfloat16 bf16;

// ---------------- device scratch (no runtime allocation) -------------------
__device__ bf16 g_F0[(size_t)BATCH * DIM];
__device__ bf16 g_F1[(size_t)BATCH * DIM];
__device__ bf16 g_F2[(size_t)BATCH * DIM];
__device__ bf16 g_H0[(size_t)BATCH * HID];
__device__ bf16 g_H1[(size_t)BATCH * HID];
__device__ bf16 g_H2[(size_t)BATCH * HID];
__device__ bf16 g_W10[DIM * HID], g_W11[DIM * HID], g_W12[DIM * HID]; // [N=256][K=1024]
__device__ bf16 g_W20[HID * DIM], g_W21[HID * DIM], g_W22[HID * DIM]; // [N=1024][K=256]
__device__ float g_comp[(size_t)BATCH * DIM];  // 128 MB

__device__ __forceinline__ float sigmoidf_(float x) {
    return 1.0f / (1.0f + expf(-x));
}

__device__ __forceinline__ void split3(float x, bf16& h, bf16& m, bf16& l) {
    h = __float2bfloat16_rn(x);
    float r1 = x - __bfloat162float(h);     // exact in fp32
    m = __float2bfloat16_rn(r1);
    float r2 = r1 - __bfloat162float(m);    // exact in fp32
    l = __float2bfloat16_rn(r2);
}

__device__ __forceinline__ void cp16(void* s, const void* gp) {
    uint32_t sa = (uint32_t)__cvta_generic_to_shared(s);
    asm volatile("cp.async.cg.shared.global [%0], [%1], 16;\n" :: "r"(sa), "l"(gp));
}
#define CP_COMMIT() asm volatile("cp.async.commit_group;\n")
#define CP_WAIT1()  asm volatile("cp.async.wait_group 1;\n")
#define CP_WAIT0()  asm volatile("cp.async.wait_group 0;\n")

// D = A*B + C, C read-only (zero quad) -> no re-zero MOVs
__device__ __forceinline__ void mma16816z(float* d, const uint32_t* a, const uint32_t* b,
                                          const float* cz) {
    asm volatile(
        "mma.sync.aligned.m16n8k16.row.col.f32.bf16.bf16.f32 "
        "{%0,%1,%2,%3}, {%4,%5,%6,%7}, {%8,%9}, {%10,%11,%12,%13};\n"
        : "=f"(d[0]), "=f"(d[1]), "=f"(d[2]), "=f"(d[3])
        : "r"(a[0]), "r"(a[1]), "r"(a[2]), "r"(a[3]), "r"(b[0]), "r"(b[1]),
          "f"(cz[0]), "f"(cz[1]), "f"(cz[2]), "f"(cz[3]));
}
// D = A*B + D (chain)
__device__ __forceinline__ void mma16816(float* d, const uint32_t* a, const uint32_t* b) {
    asm volatile(
        "mma.sync.aligned.m16n8k16.row.col.f32.bf16.bf16.f32 "
        "{%0,%1,%2,%3}, {%4,%5,%6,%7}, {%8,%9}, {%0,%1,%2,%3};\n"
        : "+f"(d[0]), "+f"(d[1]), "+f"(d[2]), "+f"(d[3])
        : "r"(a[0]), "r"(a[1]), "r"(a[2]), "r"(a[3]), "r"(b[0]), "r"(b[1]));
}

// warp-collective 4-matrix ldmatrix
__device__ __forceinline__ void ldsm4(uint32_t* r, const void* p) {
    uint32_t a = (uint32_t)__cvta_generic_to_shared(p);
    asm volatile("ldmatrix.sync.aligned.m8n8.x4.shared.b16 {%0,%1,%2,%3}, [%4];"
        : "=r"(r[0]), "=r"(r[1]), "=r"(r[2]), "=r"(r[3]) : "r"(a));
}

// scalar IEEE-rn fp32 add (no contraction)
__device__ __forceinline__ void fadds(float& d, float a) {
    asm("add.rn.f32 %0, %0, %1;" : "+f"(d) : "f"(a));
}

// ---------------- conversion kernels ---------------------------------------
__global__ __launch_bounds__(256) void cvt_f_k(const float* __restrict__ x) {
    size_t i = ((size_t)blockIdx.x * 256 + threadIdx.x) * 4;
    float4 v = *(const float4*)(x + i);
    bf16 h[4], m[4], l[4];
    split3(v.x, h[0], m[0], l[0]);
    split3(v.y, h[1], m[1], l[1]);
    split3(v.z, h[2], m[2], l[2]);
    split3(v.w, h[3], m[3], l[3]);
    *(__nv_bfloat162*)(g_F0 + i)     = __nv_bfloat162(h[0], h[1]);
    *(__nv_bfloat162*)(g_F0 + i + 2) = __nv_bfloat162(h[2], h[3]);
    *(__nv_bfloat162*)(g_F1 + i)     = __nv_bfloat162(m[0], m[1]);
    *(__nv_bfloat162*)(g_F1 + i + 2) = __nv_bfloat162(m[2], m[3]);
    *(__nv_bfloat162*)(g_F2 + i)     = __nv_bfloat162(l[0], l[1]);
    *(__nv_bfloat162*)(g_F2 + i + 2) = __nv_bfloat162(l[2], l[3]);
}

__global__ __launch_bounds__(256) void cvt_w_k(const float* __restrict__ w,
                                               bf16* __restrict__ w0,
                                               bf16* __restrict__ w1,
                                               bf16* __restrict__ w2,
                                               int K, int N) {
    int i = blockIdx.x * 256 + threadIdx.x;
    if (i >= K * N) return;
    int k = i / N, n = i % N;
    bf16 h, m, l;
    split3(w[i], h, m, l);
    w0[(size_t)n * K + k] = h;
    w1[(size_t)n * K + k] = m;
    w2[(size_t)n * K + k] = l;
}

// ---------------- tensor-core GEMM, register accumulation -------------------
// Per 16-k chunk per (mt,nt) tile: hh via zero-C MMA -> acc (fp32-rn),
// 5 corr terms (hm,hl,mh,mm,lh) D-chained within chunk only -> acc.
// R12: mt processed in PAIRS -> 4 concurrent tile chains per warp (ILP 4),
// persistent zero C-quad, scalar rn FADD extraction.
#define BM 128
#define BN 64
#define BK 16
#define SPAD 24
#define NSTAGE 3
#define STAGE_HALVES (3 * (BM + BN) * SPAD)          // 13824 bf16 per stage
#define SMEM_BYTES   (NSTAGE * STAGE_HALVES * 2)     // 82944 B

template <int EPI, int K, int N>
__global__ __launch_bounds__(256, 2) void gemm_tc(
    const bf16* __restrict__ A0g, const bf16* __restrict__ A1g, const bf16* __restrict__ A2g,
    const bf16* __restrict__ B0g, const bf16* __restrict__ B1g, const bf16* __restrict__ B2g,
    const float* __restrict__ bias,
    const float* __restrict__ F)
{
    constexpr int KT = K / BK;
    extern __shared__ __align__(16) bf16 smembuf[];
#define AS_(st,p,r,c) smembuf[((st) * STAGE_HALVES) + ((p) * BM + (r)) * SPAD + (c)]
#define BS_(st,p,r,c) smembuf[((st) * STAGE_HALVES) + (3 * BM * SPAD) + ((p) * BN + (r)) * SPAD + (c)]

    const int tid  = threadIdx.x;
    const int lane = tid & 31;
    const int wid  = tid >> 5;
    const int gq   = lane >> 2;
    const int t    = lane & 3;
    const int mW   = (wid & 1) * 64;    // warp M offset
    const int nW   = (wid >> 1) * 16;   // warp N offset

    // ldmatrix lane-address components
    const int aRowL = (lane & 7) + ((lane >> 3) & 1) * 8;
    const int aColL = (lane >> 4) * 8;
    const int bRowL = nW + ((lane >> 4) & 1) * 8 + (lane & 7);
    const int bColL = ((lane >> 3) & 1) * 8;

    const size_t mBase = (size_t)blockIdx.y * BM;
    const int    nBase = blockIdx.x * BN;

    const bf16* Ap[3] = { A0g + mBase * K, A1g + mBase * K, A2g + mBase * K };
    const bf16* Bp[3] = { B0g + (size_t)nBase * K, B1g + (size_t)nBase * K,
                          B2g + (size_t)nBase * K };

    float acc[4][2][4];
#pragma unroll
    for (int mt = 0; mt < 4; mt++)
#pragma unroll
        for (int nt = 0; nt < 2; nt++)
#pragma unroll
            for (int q = 0; q < 4; q++) acc[mt][nt][q] = 0.0f;

    const float czero[4] = {0.f, 0.f, 0.f, 0.f};   // read-only C quad

    auto load_stage = [&](int kt, int st) {
#pragma unroll
        for (int u = 0; u < 3; u++) {
            int l = tid + u * 256;
            int p = l >> 8, rr = (l & 255) >> 1, h = l & 1;
            cp16(&AS_(st, p, rr, h * 8), Ap[p] + (size_t)rr * K + kt * BK + h * 8);
        }
#pragma unroll
        for (int u = 0; u < 2; u++) {
            int l = tid + u * 256;
            if (l < 384) {
                int p = l / 128, rr = (l & 127) >> 1, h = l & 1;
                cp16(&BS_(st, p, rr, h * 8), Bp[p] + (size_t)rr * K + kt * BK + h * 8);
            }
        }
    };

    load_stage(0, 0);
    CP_COMMIT();
    if (KT > 1) { load_stage(1, 1); CP_COMMIT(); }
    CP_WAIT1();
    __syncthreads();

    for (int kt = 0; kt < KT; kt++) {
        const int st = kt % NSTAGE;
        if (kt + 2 < KT) { load_stage(kt + 2, (kt + 2) % NSTAGE); CP_COMMIT(); }

        // B fragments: 3 planes x both nt, 3 LDSM.x4
        uint32_t bfr[3][4];
#pragma unroll
        for (int p = 0; p < 3; p++)
            ldsm4(bfr[p], &BS_(st, p, bRowL, bColL));

        // mt pairs: 4 concurrent (mt,nt) tile chains
#pragma unroll
        for (int mtp = 0; mtp < 4; mtp += 2) {
            uint32_t afr[2][3][4];
#pragma unroll
            for (int i = 0; i < 2; i++)
#pragma unroll
                for (int p = 0; p < 3; p++)
                    ldsm4(afr[i][p], &AS_(st, p, mW + (mtp + i) * 16 + aRowL, aColL));

            float d[2][2][4], c[2][2][4];
            // 4 independent hh MMAs
#pragma unroll
            for (int i = 0; i < 2; i++)
#pragma unroll
                for (int nt = 0; nt < 2; nt++) {
                    const uint32_t b0[2] = { bfr[0][nt * 2], bfr[0][nt * 2 + 1] };
                    mma16816z(d[i][nt], afr[i][0], b0, czero);
                }
            // 4 independent 5-deep corr chains
#pragma unroll
            for (int i = 0; i < 2; i++)
#pragma unroll
                for (int nt = 0; nt < 2; nt++) {
                    const uint32_t b0[2] = { bfr[0][nt * 2], bfr[0][nt * 2 + 1] };
                    const uint32_t b1[2] = { bfr[1][nt * 2], bfr[1][nt * 2 + 1] };
                    const uint32_t b2[2] = { bfr[2][nt * 2], bfr[2][nt * 2 + 1] };
                    mma16816z(c[i][nt], afr[i][0], b1, czero);   // hm
                    mma16816(c[i][nt], afr[i][0], b2);           // hl
                    mma16816(c[i][nt], afr[i][1], b0);           // mh
                    mma16816(c[i][nt], afr[i][1], b1);           // mm
                    mma16816(c[i][nt], afr[i][2], b0);           // lh
                }
            // extraction: acc += d; acc += c  (IEEE-rn scalar adds)
#pragma unroll
            for (int i = 0; i < 2; i++)
#pragma unroll
                for (int nt = 0; nt < 2; nt++)
#pragma unroll
                    for (int q = 0; q < 4; q++) {
                        fadds(acc[mtp + i][nt][q], d[i][nt][q]);
                        fadds(acc[mtp + i][nt][q], c[i][nt][q]);
                    }
        }

        if (kt + 1 < KT) {
            if (kt + 2 < KT) CP_WAIT1();
            else             CP_WAIT0();
            __syncthreads();
        }
    }

    // epilogue
#pragma unroll
    for (int mt = 0; mt < 4; mt++) {
#pragma unroll
        for (int nt = 0; nt < 2; nt++) {
            size_t r0 = mBase + mW + mt * 16 + gq;
            size_t r1 = r0 + 8;
            int c = nBase + nW + nt * 8 + 2 * t;
            float b0 = __ldg(bias + c), b1 = __ldg(bias + c + 1);
            float x00 = acc[mt][nt][0] + b0, x01 = acc[mt][nt][1] + b1;
            float x10 = acc[mt][nt][2] + b0, x11 = acc[mt][nt][3] + b1;
            if (EPI == 0) {
                float hv[4] = { fmaxf(x00, 0.f), fmaxf(x01, 0.f),
                                fmaxf(x10, 0.f), fmaxf(x11, 0.f) };
                bf16 h[4], m[4], l[4];
#pragma unroll
                for (int q = 0; q < 4; q++) split3(hv[q], h[q], m[q], l[q]);
                *(__nv_bfloat162*)(g_H0 + r0 * N + c) = __nv_bfloat162(h[0], h[1]);
                *(__nv_bfloat162*)(g_H0 + r1 * N + c) = __nv_bfloat162(h[2], h[3]);
                *(__nv_bfloat162*)(g_H1 + r0 * N + c) = __nv_bfloat162(m[0], m[1]);
                *(__nv_bfloat162*)(g_H1 + r1 * N + c) = __nv_bfloat162(m[2], m[3]);
                *(__nv_bfloat162*)(g_H2 + r0 * N + c) = __nv_bfloat162(l[0], l[1]);
                *(__nv_bfloat162*)(g_H2 + r1 * N + c) = __nv_bfloat162(l[2], l[3]);
            } else {
                float2 f0 = *(const float2*)(F + r0 * N + c);
                float2 f1 = *(const float2*)(F + r1 * N + c);
                float g00 = f0.x * sigmoidf_(x00), g01 = f0.y * sigmoidf_(x01);
                float g10 = f1.x * sigmoidf_(x10), g11 = f1.y * sigmoidf_(x11);
                float2 o0, o1;
                o0.x = (g00 > 0.3f) ? 0.f : g00;  o0.y = (g01 > 0.3f) ? 0.f : g01;
                o1.x = (g10 > 0.3f) ? 0.f : g10;  o1.y = (g11 > 0.3f) ? 0.f : g11;
                *(float2*)(g_comp + r0 * N + c) = o0;
                *(float2*)(g_comp + r1 * N + c) = o1;
            }
        }
    }
#undef AS_
#undef BS_
}

// ---------------- row-wise post-processing ----------------------------------
#define R3 8

__global__ __launch_bounds__(256) void rowpost_k(
    const float* __restrict__ w_r1, const float* __restrict__ b_r1,
    const float* __restrict__ w_r2, const float* __restrict__ b_r2,
    const float* __restrict__ w_m1, const float* __restrict__ b_m1,
    const float* __restrict__ w_m2, const float* __restrict__ b_m2,
    float* __restrict__ out)
{
    const int tid  = threadIdx.x;
    const int lane = tid & 31;
    const int wid  = tid >> 5;

    __shared__ float sA[8], sB[8], sC[8], sD[8];

    float wr2[16][4];
#pragma unroll
    for (int k = 0; k < 16; k++)
#pragma unroll
        for (int j = 0; j < 4; j++)
            wr2[k][j] = __ldg(w_r2 + k * DIM + tid + 256 * j);
    float br2r[4];
#pragma unroll
    for (int j = 0; j < 4; j++) br2r[j] = __ldg(b_r2 + tid + 256 * j);

    for (int rr = 0; rr < R3; rr++) {
        size_t row = (size_t)blockIdx.x * R3 + rr;
        const float* cr = g_comp + row * DIM;

        __syncthreads();

        float v[4];
#pragma unroll
        for (int j = 0; j < 4; j++) v[j] = cr[tid + 256 * j];

        float cnt = 0.0f;
#pragma unroll
        for (int j = 0; j < 4; j++) cnt += (fabsf(v[j]) < 0.1f) ? 1.0f : 0.0f;
#pragma unroll
        for (int o = 16; o; o >>= 1) cnt += __shfl_xor_sync(0xffffffffu, cnt, o);
        if (lane == 0) sD[wid] = cnt;
        __syncthreads();
        cnt = 0.0f;
#pragma unroll
        for (int w = 0; w < 8; w++) cnt += sD[w];
        float cur_sp = cnt * (1.0f / 1024.0f);

        float hr[16];
#pragma unroll
        for (int k = 0; k < 16; k++) {
            float x = fmaf(cur_sp, __ldg(w_r1 + k),
                      fmaf(0.1f, __ldg(w_r1 + 16 + k), __ldg(b_r1 + k)));
            hr[k] = fmaxf(x, 0.0f);
        }

        float dyn[4];
        float s1 = 0.0f, s2 = 0.0f, mx = -INFINITY;
#pragma unroll
        for (int j = 0; j < 4; j++) {
            float a = br2r[j];
#pragma unroll
            for (int k = 0; k < 16; k++) a = fmaf(hr[k], wr2[k][j], a);
            float rw = sigmoidf_(a);
            float d  = v[j] * rw;
            dyn[j] = d;
            s1 += d;
            s2 = fmaf(d, d, s2);
            mx = fmaxf(mx, d);
        }
#pragma unroll
        for (int o = 16; o; o >>= 1) {
            s1 += __shfl_xor_sync(0xffffffffu, s1, o);
            s2 += __shfl_xor_sync(0xffffffffu, s2, o);
            mx = fmaxf(mx, __shfl_xor_sync(0xffffffffu, mx, o));
        }
        if (lane == 0) { sA[wid] = s1; sB[wid] = s2; sC[wid] = mx; }
        __syncthreads();
        s1 = 0.0f; s2 = 0.0f; mx = -INFINITY;
#pragma unroll
        for (int w = 0; w < 8; w++) {
            s1 += sA[w]; s2 += sB[w]; mx = fmaxf(mx, sC[w]);
        }

        float fmean = s1 * (1.0f / 1024.0f);
        float var   = (s2 - s1 * fmean) * (1.0f / 1023.0f);   // ddof=1
        var = fmaxf(var, 0.0f);
        float fstd = sqrtf(var);

        float a2 = __ldg(b_m2);
#pragma unroll
        for (int k = 0; k < 16; k++) {
            float x = fmaf(fmean, __ldg(w_m1 + k),
                      fmaf(fstd, __ldg(w_m1 + 16 + k),
                      fmaf(mx,   __ldg(w_m1 + 32 + k), __ldg(b_m1 + k))));
            a2 = fmaf(fmaxf(x, 0.0f), __ldg(w_m2 + k), a2);
        }
        float thr = sigmoidf_(a2);

        float* orow = out + row * DIM;
#pragma unroll
        for (int j = 0; j < 4; j++)
            orow[tid + 256 * j] = (fabsf(dyn[j]) > thr) ? dyn[j] : 0.0f;
    }
}

// ---------------- launch -----------------------------------------------------
extern "C" void kernel_launch(void* const* d_in, const int* in_sizes, int n_in,
                              void* d_out, int out_size)
{
    const float* F   = (const float*)d_in[0];
    const float* wg1 = (const float*)d_in[1];
    const float* bg1 = (const float*)d_in[2];
    const float* wg2 = (const float*)d_in[3];
    const float* bg2 = (const float*)d_in[4];
    // d_in[5..8] = competition weights: dead code (win == False always)
    const float* wr1 = (const float*)d_in[9];
    const float* br1 = (const float*)d_in[10];
    const float* wr2 = (const float*)d_in[11];
    const float* br2 = (const float*)d_in[12];
    const float* wm1 = (const float*)d_in[13];
    const float* bm1 = (const float*)d_in[14];
    const float* wm2 = (const float*)d_in[15];
    const float* bm2 = (const float*)d_in[16];
    float* out = (float*)d_out;
    (void)in_sizes; (void)n_in; (void)out_size;

    bf16 *W10, *W11, *W12, *W20, *W21, *W22, *F0, *F1, *F2, *H0, *H1, *H2;
    cudaGetSymbolAddress((void**)&W10, g_W10);
    cudaGetSymbolAddress((void**)&W11, g_W11);
    cudaGetSymbolAddress((void**)&W12, g_W12);
    cudaGetSymbolAddress((void**)&W20, g_W20);
    cudaGetSymbolAddress((void**)&W21, g_W21);
    cudaGetSymbolAddress((void**)&W22, g_W22);
    cudaGetSymbolAddress((void**)&F0, g_F0);
    cudaGetSymbolAddress((void**)&F1, g_F1);
    cudaGetSymbolAddress((void**)&F2, g_F2);
    cudaGetSymbolAddress((void**)&H0, g_H0);
    cudaGetSymbolAddress((void**)&H1, g_H1);
    cudaGetSymbolAddress((void**)&H2, g_H2);

    static int attr_done = 0;
    if (!attr_done) {
        cudaFuncSetAttribute(gemm_tc<0, DIM, HID>,
                             cudaFuncAttributeMaxDynamicSharedMemorySize, SMEM_BYTES);
        cudaFuncSetAttribute(gemm_tc<1, HID, DIM>,
                             cudaFuncAttributeMaxDynamicSharedMemorySize, SMEM_BYTES);
        attr_done = 1;
    }

    cvt_w_k<<<(DIM * HID + 255) / 256, 256>>>(wg1, W10, W11, W12, DIM, HID);
    cvt_w_k<<<(HID * DIM + 255) / 256, 256>>>(wg2, W20, W21, W22, HID, DIM);
    cvt_f_k<<<(BATCH * DIM / 4) / 256, 256>>>(F);

    // GEMM1: H = relu(F @ Wg1 + bg1)
    gemm_tc<0, DIM, HID><<<dim3(HID / BN, BATCH / BM), 256, SMEM_BYTES>>>(
        F0, F1, F2, W10, W11, W12, bg1, nullptr);
    // GEMM2: comp = thresh(F * sigmoid(H @ Wg2 + bg2))
    gemm_tc<1, HID, DIM><<<dim3(DIM / BN, BATCH / BM), 256, SMEM_BYTES>>>(
        H0, H1, H2, W20, W21, W22, bg2, F);
    // row-wise post-processing
    rowpost_k<<<BATCH / R3, 256>>>(wr1, br1, wr2, br2, wm1, bm1, wm2, bm2, out);
}